// round 17
// baseline (speedup 1.0000x reference)
#include <cuda_runtime.h>
#include <cuda_bf16.h>
#include <cuda_fp16.h>
#include <stdint.h>

#define B_     2
#define N_     65536
#define M_     16384
#define K_     32
#define KP_    15
#define DIN_   64
#define DOUT_  128
#define KTOT   960           // KP_*DIN_
#define SHADOW (-1000.0f)

// ---------------------------------------------------------------------------
// Scratch (__device__ globals per no-allocation rule)
// ---------------------------------------------------------------------------
__device__ __align__(16) __half g_featTh[(size_t)B_ * N_ * DIN_];  // 16.8 MB fp16
__device__ __align__(16) __half g_bh[DOUT_ * KTOT];                // W^T fp16

// ---------------------------------------------------------------------------
// helpers
// ---------------------------------------------------------------------------
__device__ __forceinline__ uint32_t smem_u32(const void* p) {
    uint32_t a;
    asm("{ .reg .u64 t; cvta.to.shared.u64 t, %1; cvt.u32.u64 %0, t; }"
        : "=r"(a) : "l"(p));
    return a;
}
__device__ __forceinline__ void ldsm4(uint32_t& r0, uint32_t& r1,
                                      uint32_t& r2, uint32_t& r3, uint32_t addr) {
    asm volatile("ldmatrix.sync.aligned.m8n8.x4.shared.b16 {%0,%1,%2,%3}, [%4];"
                 : "=r"(r0), "=r"(r1), "=r"(r2), "=r"(r3) : "r"(addr));
}
__device__ __forceinline__ void ldsm4t(uint32_t& r0, uint32_t& r1,
                                       uint32_t& r2, uint32_t& r3, uint32_t addr) {
    asm volatile("ldmatrix.sync.aligned.m8n8.x4.trans.shared.b16 {%0,%1,%2,%3}, [%4];"
                 : "=r"(r0), "=r"(r1), "=r"(r2), "=r"(r3) : "r"(addr));
}
__device__ __forceinline__ void mma_f16(float* c, const uint32_t* a,
                                        const uint32_t* b) {
    asm volatile("mma.sync.aligned.m16n8k16.row.col.f32.f16.f16.f32 "
                 "{%0,%1,%2,%3}, {%4,%5,%6,%7}, {%8,%9}, {%0,%1,%2,%3};"
                 : "+f"(c[0]), "+f"(c[1]), "+f"(c[2]), "+f"(c[3])
                 : "r"(a[0]), "r"(a[1]), "r"(a[2]), "r"(a[3]),
                   "r"(b[0]), "r"(b[1]));
}
__device__ __forceinline__ void cpasync16(uint32_t dst, const void* src) {
    asm volatile("cp.async.ca.shared.global [%0], [%1], 16;" :: "r"(dst), "l"(src));
}
__device__ __forceinline__ void cp_commit() {
    asm volatile("cp.async.commit_group;" ::: "memory");
}
__device__ __forceinline__ void cp_wait2() {
    asm volatile("cp.async.wait_group 2;" ::: "memory");
}
__device__ __forceinline__ void cp_wait1() {
    asm volatile("cp.async.wait_group 1;" ::: "memory");
}
__device__ __forceinline__ void cp_wait0() {
    asm volatile("cp.async.wait_group 0;" ::: "memory");
}
__device__ __forceinline__ uint32_t pkhf2(float a, float b) {
    __half2 t = __floats2half2_rn(a, b);
    return *(uint32_t*)&t;
}

// ---------------------------------------------------------------------------
// Kernel 1: transpose features [B][Din][N] -> g_featTh [B][N][Din] (fp16)
// ---------------------------------------------------------------------------
__global__ void transpose_feat_kernel(const float* __restrict__ f)
{
    __shared__ float tile[32][33];
    const int b  = blockIdx.z;
    const int n0 = blockIdx.x * 32;
    const int d0 = blockIdx.y * 32;
    const int x = threadIdx.x, y = threadIdx.y;

    #pragma unroll
    for (int i = y; i < 32; i += 8)
        tile[i][x] = f[((size_t)b * DIN_ + (d0 + i)) * N_ + n0 + x];
    __syncthreads();
    #pragma unroll
    for (int i = y; i < 32; i += 8)
        g_featTh[((size_t)b * N_ + (n0 + i)) * DIN_ + d0 + x] =
            __float2half_rn(tile[x][i]);
}

// ---------------------------------------------------------------------------
// Kernel 1b: weights [Kp][Din][Dout] -> g_bh [Dout rows][KTOT cols] (fp16)
// ---------------------------------------------------------------------------
__global__ void prep_w_kernel(const float* __restrict__ w)
{
    const int e = blockIdx.x * 256 + threadIdx.x;
    if (e >= KP_ * DIN_ * DOUT_) return;
    const int kp = e / DOUT_, o = e % DOUT_;
    g_bh[o * KTOT + kp] = __float2half_rn(w[e]);
}

// ---------------------------------------------------------------------------
// Fused kernel: einsum1 (per-point tensor mma) + GEMM, A tile lives in smem.
//   CTA = 64 points (one GEMM M-tile), 512 threads (16 warps).
//   Phase A: warp computes 4 points (R16 kernel2 body), writes weighted rows
//            straight into smem A [64 x 960] (stride 968, ldsm-safe).
//   Phase B: C[64x128] = A_smem @ W; 4-stage cp.async B ring (prefetch
//            starts at kernel entry), warp tile 16x32.
// NOTE: neighbor_indices is int32 (JAX canonicalizes int64 -> int32).
// ---------------------------------------------------------------------------
#define FPTS    64
#define FSTR    72                        // gather smem row stride (fp16)
#define WSTR    40                        // w smem row stride (fp16)
#define STG_F   (16 * FSTR * 2)           // 2304
#define STG_W   (16 * WSTR * 2)           // 1280
#define STG_BYTES (STG_F + STG_W)         // 3584 per warp
#define ASTR    968                       // A row stride (elems); 1936B rows
#define A_BYTES (FPTS * ASTR * 2)         // 123904
#define BK      32
#define NCHUNK  (KTOT / BK)               // 30
#define BSTG    40                        // B smem row stride
#define B_ARR   (128 * BSTG * 2)          // 10240 per stage
#define NBSTAGE 4
#define FUSED_SMEM (A_BYTES + NBSTAGE * B_ARR + 16 * STG_BYTES)  // 222208

__global__ __launch_bounds__(512)
void kpconv_fused(const float* __restrict__ points_xyz,
                  const float* __restrict__ center_xyz,
                  const int* __restrict__ nidx,
                  const float* __restrict__ kernel_points,
                  float* __restrict__ out)
{
    extern __shared__ __align__(16) char sm[];
    __half* Asm = (__half*)sm;
    char*   Bsm = sm + A_BYTES;
    char*   stg = sm + A_BYTES + NBSTAGE * B_ARR;

    const int tid  = threadIdx.x;
    const int wid  = tid >> 5;
    const int lane = tid & 31;
    const size_t rowBase = (size_t)blockIdx.x * FPTS;
    const int b = (int)(rowBase >> 14);        // 64 | 16384: one batch per CTA

    // ---- B prefetch (chunks 0,1) — lands during phase A
    auto issue_b = [&](int c, int stage) {
        const uint32_t sb = smem_u32(Bsm) + stage * B_ARR;
        const int row = tid >> 2, seg = tid & 3;   // 512 threads = 512 x 16B
        cpasync16(sb + (row * BSTG + seg * 8) * 2,
                  g_bh + (size_t)row * KTOT + c * BK + seg * 8);
        cp_commit();
    };
    issue_b(0, 0);
    issue_b(1, 1);

    // ---- per-lane ldmatrix patterns (shared by both phases)
    const int ltile = lane >> 3, lr = lane & 7;
    const int aRow = (ltile & 1) * 8 + lr;
    const int aCol = (ltile >> 1) * 8;

    // ======================= Phase A: 4 points per warp ====================
    {
        __half* sF = (__half*)(stg + wid * STG_BYTES);
        __half* sW = sF + 16 * FSTR;
        const int bRowA = (ltile & 1) * 8 + lr;    // B(feat) trans pattern
        const int bColA = (ltile >> 1) * 8;
        const int grow = lane >> 3;                 // gather row in group
        const int gseg = lane & 7;                  // uint4 slot in 128B row
        const uint4* gfb = (const uint4*)(g_featTh + (size_t)b * N_ * DIN_);
        const int r  = lane >> 2;
        const int cb = 2 * (lane & 3);

        for (int pi = 0; pi < 4; ++pi) {
            const int ptl = wid * 4 + pi;          // local point 0..63
            const int bm  = (int)rowBase + ptl;

            // phase 1: lane = k
            const int ii0 = nidx[(size_t)bm * K_ + lane];
            const bool valid = (unsigned)ii0 < (unsigned)N_;
            const int idx = valid ? ii0 : 0;
            float px = SHADOW, py = SHADOW, pz = SHADOW;
            if (valid) {
                const float* pp = points_xyz + ((size_t)b * N_ + ii0) * 3;
                px = pp[0]; py = pp[1]; pz = pp[2];
            }
            const float rx = px - center_xyz[bm * 3 + 0];
            const float ry = py - center_xyz[bm * 3 + 1];
            const float rz = pz - center_xyz[bm * 3 + 2];
            float md = sqrtf(rx * rx + ry * ry + rz * rz);
            #pragma unroll
            for (int o = 16; o; o >>= 1)
                md = fmaxf(md, __shfl_xor_sync(0xffffffffu, md, o));
            const float inv = 1.0f / (md / 2.1f + 1e-5f);

            // phase 2: w[p][k=lane] fp16; row 15 zero
            #pragma unroll
            for (int p = 0; p < KP_; ++p) {
                const float kx = kernel_points[p * 3 + 0] * md;
                const float ky = kernel_points[p * 3 + 1] * md;
                const float kz = kernel_points[p * 3 + 2] * md;
                const float dx = rx - kx, dy = ry - ky, dz = rz - kz;
                float w = 1.0f - sqrtf(dx * dx + dy * dy + dz * dz) * inv;
                w = valid ? fmaxf(w, 0.0f) : 0.0f;
                sW[p * WSTR + lane] = __float2half_rn(w);
            }
            sW[15 * WSTR + lane] = __float2half_rn(0.0f);

            float acc[8][4];
            #pragma unroll
            for (int j = 0; j < 8; ++j)
                #pragma unroll
                for (int q = 0; q < 4; ++q) acc[j][q] = 0.0f;

            #pragma unroll
            for (int kc = 0; kc < 2; ++kc) {
                #pragma unroll
                for (int pass = 0; pass < 4; ++pass) {
                    const int kl = pass * 4 + grow;
                    const int ik = __shfl_sync(0xffffffffu, idx, kc * 16 + kl);
                    *(uint4*)&sF[kl * FSTR + gseg * 8] = gfb[(size_t)ik * 8 + gseg];
                }
                __syncwarp();

                uint32_t ah[4];
                const uint32_t aOff = (uint32_t)(aRow * WSTR + kc * 16 + aCol) * 2;
                ldsm4(ah[0], ah[1], ah[2], ah[3], smem_u32(sW) + aOff);
                #pragma unroll
                for (int g = 0; g < 4; ++g) {
                    const uint32_t bOff =
                        (uint32_t)(bRowA * FSTR + g * 16 + bColA) * 2;
                    uint32_t bf[4];
                    ldsm4t(bf[0], bf[1], bf[2], bf[3], smem_u32(sF) + bOff);
                    #pragma unroll
                    for (int half = 0; half < 2; ++half)
                        mma_f16(acc[2 * g + half], ah, bf + 2 * half);
                }
                __syncwarp();
            }

            // write weighted row straight into smem A tile (skip p==15)
            __half* Arow = Asm + (size_t)ptl * ASTR;
            #pragma unroll
            for (int nt = 0; nt < 8; ++nt) {
                const int d0 = nt * 8 + cb;
                *(uint32_t*)&Arow[r * 64 + d0] = pkhf2(acc[nt][0], acc[nt][1]);
                if (r < 7)   // p = r+8 in 8..14; p==15 would overflow stride
                    *(uint32_t*)&Arow[(r + 8) * 64 + d0] =
                        pkhf2(acc[nt][2], acc[nt][3]);
            }
            __syncwarp();
        }
    }
    __syncthreads();     // A tile complete

    // ======================= Phase B: GEMM ================================
    const int wm = wid & 3;           // m-tile: wm*16
    const int wn = wid >> 2;          // n-tile: wn*32
    const int bRow = (ltile >> 1) * 8 + lr;
    const int bCol = (ltile & 1) * 8;

    float acc[4][4];
    #pragma unroll
    for (int j = 0; j < 4; ++j)
        #pragma unroll
        for (int q = 0; q < 4; ++q) acc[j][q] = 0.0f;

    const uint32_t aBase = smem_u32(Asm);
    const uint32_t bBase = smem_u32(Bsm);

    auto compute_chunk = [&](int c, int stage) {
        const uint32_t pB = bBase + stage * B_ARR;
        #pragma unroll
        for (int kk = 0; kk < 2; ++kk) {
            const int kcol = kk * 16;
            uint32_t af[4];
            {
                const int row = wm * 16 + aRow;
                const uint32_t off =
                    (uint32_t)(row * ASTR + c * BK + kcol + aCol) * 2;
                ldsm4(af[0], af[1], af[2], af[3], aBase + off);
            }
            #pragma unroll
            for (int g = 0; g < 2; ++g) {
                const int row = wn * 32 + g * 16 + bRow;
                const uint32_t off = (uint32_t)(row * BSTG + kcol + bCol) * 2;
                uint32_t bf[4];
                ldsm4(bf[0], bf[1], bf[2], bf[3], pB + off);
                #pragma unroll
                for (int half = 0; half < 2; ++half)
                    mma_f16(acc[2 * g + half], af, bf + 2 * half);
            }
        }
    };

    for (int c = 0; c < NCHUNK - 2; ++c) {
        issue_b(c + 2, (c + 2) & 3);
        cp_wait2();
        __syncthreads();
        compute_chunk(c, c & 3);
    }
    cp_wait1();
    __syncthreads();
    compute_chunk(NCHUNK - 2, (NCHUNK - 2) & 3);
    cp_wait0();
    __syncthreads();
    compute_chunk(NCHUNK - 1, (NCHUNK - 1) & 3);

    // epilogue
    const int bb     = (int)(rowBase >> 14);
    const int mLocal = (int)(rowBase & 16383);
    #pragma unroll
    for (int nt = 0; nt < 4; ++nt) {
        const int m0 = mLocal + wm * 16 + (lane >> 2);
        const int n0 = wn * 32 + nt * 8 + 2 * (lane & 3);
        float* o0 = out + ((size_t)bb * DOUT_ + n0) * M_ + m0;
        o0[0]      = acc[nt][0];
        o0[M_]     = acc[nt][1];
        o0[8]      = acc[nt][2];
        o0[M_ + 8] = acc[nt][3];
    }
}

// ---------------------------------------------------------------------------
extern "C" void kernel_launch(void* const* d_in, const int* in_sizes, int n_in,
                              void* d_out, int out_size)
{
    // Dispatch inputs by (pairwise-distinct) element count:
    const float* points_xyz    = nullptr;
    const float* features      = nullptr;
    const float* center_xyz    = nullptr;
    const int*   neighbor_idx  = nullptr;
    const float* kernel_points = nullptr;
    const float* weights       = nullptr;

    for (int i = 0; i < n_in; i++) {
        switch (in_sizes[i]) {
            case 393216:  points_xyz    = (const float*)d_in[i]; break;
            case 8388608: features      = (const float*)d_in[i]; break;
            case 98304:   center_xyz    = (const float*)d_in[i]; break;
            case 1048576: neighbor_idx  = (const int*)d_in[i];   break;
            case 45:      kernel_points = (const float*)d_in[i]; break;
            case 122880:  weights       = (const float*)d_in[i]; break;
            default: break;
        }
    }
    float* out = (float*)d_out;

    cudaFuncSetAttribute(kpconv_fused,
                         cudaFuncAttributeMaxDynamicSharedMemorySize, FUSED_SMEM);
    cudaFuncSetAttribute(kpconv_fused,
                         cudaFuncAttributePreferredSharedMemoryCarveout, 100);

    dim3 g1(N_ / 32, DIN_ / 32, B_);
    transpose_feat_kernel<<<g1, dim3(32, 8)>>>(features);

    prep_w_kernel<<<(KP_ * DIN_ * DOUT_ + 255) / 256, 256>>>(weights);

    kpconv_fused<<<(B_ * M_) / FPTS, 512, FUSED_SMEM>>>(
        points_xyz, center_xyz, neighbor_idx, kernel_points, out);
}